// round 13
// baseline (speedup 1.0000x reference)
#include <cuda_runtime.h>
#include <cuda_pipeline.h>
#include <math.h>

// ---------------- constants ----------------
#define BB 32
#define TT 250
#define CLASSES 25
#define UNITS 512
#define NH 2048           // 4*UNITS
#define CELL 64
#define HEADS 4
#define FEAT 128
#define XDIM 153          // FEAT + CLASSES
#define RVDIM 256         // HEADS*CELL
#define KTOT 960          // padded (XDIM + RVDIM + UNITS = 921 -> 960)
#define KC 320            // K-chunk for z GEMM (3 chunks)
#define PDIM 320          // (HEADS+1)*CELL
#define HRV 768           // UNITS + RVDIM
#define EPS_BN 1e-3f

// ---------------- device scratch ----------------
__device__ alignas(16) float g_a1[8000 * 13 * 13 * 8];
__device__ alignas(16) float g_a2[8000 * 6 * 6 * 16];
__device__ alignas(16) float g_xfeat[8000 * FEAT];
__device__ alignas(16) float g_Wcomb[KTOT * NH];
__device__ alignas(16) float g_inp[BB * KTOT];
__device__ alignas(16) float g_zpart[3 * BB * NH];
__device__ alignas(16) float g_c[2 * BB * UNITS];        // parity double buffer
__device__ alignas(256) float g_wvstore[BB * TT * CELL]; // raw wv rows
__device__ alignas(256) float g_wvn[BB * TT * CELL];     // normalized wv rows
__device__ alignas(16) float g_hist[TT * BB * HRV];
__device__ alignas(16) float g_outbuf[8000 * UNITS];

__device__ __forceinline__ float sigm(float x) { return 1.f / (1.f + __expf(-x)); }
// overflow-safe fast tanh (validated in R11: rel_err ~9.8e-8)
__device__ __forceinline__ float ftanh(float x) {
    float e = __expf(-2.f * fabsf(x));
    float r = (1.f - e) / (1.f + e);
    return copysignf(r, x);
}

// ---------------- conv frontend ----------------
__global__ void conv1_k(const float* __restrict__ img, const float* __restrict__ k1,
                        const float* __restrict__ cb, const float* __restrict__ g,
                        const float* __restrict__ be, const float* __restrict__ mm,
                        const float* __restrict__ mv) {
    int idx = blockIdx.x * 256 + threadIdx.x;
    if (idx >= 8000 * 13 * 13 * 8) return;
    int co = idx & 7;
    int t2 = idx >> 3;
    int x = t2 % 13; t2 /= 13;
    int y = t2 % 13; t2 /= 13;
    int bt = t2;
    const float* ip = img + ((size_t)bt * 28 + 2 * y) * 28 + 2 * x;
    float acc = 0.f;
#pragma unroll
    for (int dy = 0; dy < 3; dy++)
#pragma unroll
        for (int dx = 0; dx < 3; dx++)
            acc = fmaf(ip[dy * 28 + dx], k1[(dy * 3 + dx) * 8 + co], acc);
    float sc = g[co] * rsqrtf(mv[co] + EPS_BN);
    float val = (acc + cb[co] - mm[co]) * sc + be[co];
    g_a1[idx] = fmaxf(val, 0.f);
}

__global__ void conv2_k(const float* __restrict__ k2, const float* __restrict__ cb,
                        const float* __restrict__ g, const float* __restrict__ be,
                        const float* __restrict__ mm, const float* __restrict__ mv) {
    int idx = blockIdx.x * 256 + threadIdx.x;
    if (idx >= 8000 * 6 * 6 * 16) return;
    int co = idx & 15;
    int t2 = idx >> 4;
    int x = t2 % 6; t2 /= 6;
    int y = t2 % 6; t2 /= 6;
    int bt = t2;
    const float* ip = g_a1 + (((size_t)bt * 13 + 2 * y) * 13 + 2 * x) * 8;
    float acc = 0.f;
#pragma unroll
    for (int dy = 0; dy < 3; dy++)
#pragma unroll
        for (int dx = 0; dx < 3; dx++) {
            const float* p = ip + (dy * 13 + dx) * 8;
            const float* w = k2 + ((dy * 3 + dx) * 8) * 16 + co;
#pragma unroll
            for (int ci = 0; ci < 8; ci++)
                acc = fmaf(p[ci], w[ci * 16], acc);
        }
    float sc = g[co] * rsqrtf(mv[co] + EPS_BN);
    float val = (acc + cb[co] - mm[co]) * sc + be[co];
    g_a2[idx] = fmaxf(val, 0.f);
}

__global__ void conv3_k(const float* __restrict__ k3, const float* __restrict__ cb,
                        const float* __restrict__ g, const float* __restrict__ be,
                        const float* __restrict__ mm, const float* __restrict__ mv) {
    int idx = blockIdx.x * 256 + threadIdx.x;
    if (idx >= 8000 * 2 * 2 * 32) return;
    int co = idx & 31;
    int x = (idx >> 5) & 1;
    int y = (idx >> 6) & 1;
    int bt = idx >> 7;
    const float* ip = g_a2 + (((size_t)bt * 6 + 2 * y) * 6 + 2 * x) * 16;
    float acc = 0.f;
#pragma unroll
    for (int dy = 0; dy < 3; dy++)
#pragma unroll
        for (int dx = 0; dx < 3; dx++) {
            const float* p = ip + (dy * 6 + dx) * 16;
            const float* w = k3 + ((dy * 3 + dx) * 16) * 32 + co;
#pragma unroll
            for (int ci = 0; ci < 16; ci++)
                acc = fmaf(p[ci], w[ci * 32], acc);
        }
    float sc = g[co] * rsqrtf(mv[co] + EPS_BN);
    float val = (acc + cb[co] - mm[co]) * sc + be[co];
    g_xfeat[idx] = fmaxf(val, 0.f);
}

// ---------------- Wcomb build + init ----------------
__global__ void build_wcomb(const float* __restrict__ Wx, const float* __restrict__ Wh) {
    int idx = blockIdx.x * 256 + threadIdx.x;
    if (idx >= KTOT * NH) return;
    int r = idx >> 11;
    int c = idx & 2047;
    float v = 0.f;
    if (r < 409) v = Wx[r * NH + c];
    else if (r < 921) v = Wh[(r - 409) * NH + c];
    g_Wcomb[idx] = v;
}

__global__ void k_init(const int* __restrict__ labels) {
    int b = blockIdx.x;
    for (int u = threadIdx.x; u < UNITS; u += 256) g_c[b * UNITS + u] = 0.f;  // parity 0
    int lab = labels[b * TT];  // t=0
    for (int k = threadIdx.x; k < KTOT; k += 256) {
        float v = 0.f;
        if (k < FEAT) v = g_xfeat[(size_t)b * TT * FEAT + k];
        else if (k < XDIM) v = (k - FEAT == lab) ? 1.f : 0.f;
        g_inp[b * KTOT + k] = v;
    }
}

// ---------------- K1: partial z GEMM ----------------
// grid (64, 3), block 256. Block = 32 cols x 32 batches over one K-chunk.
__global__ void __launch_bounds__(256) k1_zpart() {
    __shared__ alignas(16) float s_in[BB * KC];  // 40 KB
    int kc = blockIdx.y;
    int kbase = kc * KC;
    for (int i = threadIdx.x; i < (BB * KC) / 4; i += 256) {
        int b = i / (KC / 4);
        int k4 = i - b * (KC / 4);
        ((float4*)s_in)[i] = *(const float4*)(g_inp + b * KTOT + kbase + 4 * k4);
    }
    __syncthreads();
    int lane = threadIdx.x & 31;
    int bg = threadIdx.x >> 5;
    int col = (blockIdx.x << 5) + lane;
    const float* wp = g_Wcomb + (size_t)kbase * NH + col;
    const float* ip = s_in + bg * 4 * KC;
    float a0 = 0.f, a1 = 0.f, a2 = 0.f, a3 = 0.f;
#pragma unroll 8
    for (int k = 0; k < KC; k += 4) {
        float w0 = wp[0], w1 = wp[NH], w2 = wp[2 * NH], w3 = wp[3 * NH];
        wp += 4 * NH;
        float4 x0 = *(const float4*)(ip + k);
        float4 x1 = *(const float4*)(ip + KC + k);
        float4 x2 = *(const float4*)(ip + 2 * KC + k);
        float4 x3 = *(const float4*)(ip + 3 * KC + k);
        a0 = fmaf(w0, x0.x, a0); a0 = fmaf(w1, x0.y, a0); a0 = fmaf(w2, x0.z, a0); a0 = fmaf(w3, x0.w, a0);
        a1 = fmaf(w0, x1.x, a1); a1 = fmaf(w1, x1.y, a1); a1 = fmaf(w2, x1.z, a1); a1 = fmaf(w3, x1.w, a1);
        a2 = fmaf(w0, x2.x, a2); a2 = fmaf(w1, x2.y, a2); a2 = fmaf(w2, x2.z, a2); a2 = fmaf(w3, x2.w, a2);
        a3 = fmaf(w0, x3.x, a3); a3 = fmaf(w1, x3.y, a3); a3 = fmaf(w2, x3.z, a3); a3 = fmaf(w3, x3.w, a3);
    }
    int b0 = bg << 2;
    float* zp = g_zpart + ((size_t)(kc * BB + b0)) * NH + col;
    zp[0] = a0; zp[NH] = a1; zp[2 * NH] = a2; zp[3 * NH] = a3;
}

// ---------------- K2 fused: gates + Wp chunk + norm + attention ----------------
// grid 160 = (b in 0..31) x (chunk 0..4).
// chunk 0: writes c, h (inp/hist), wv, wvn, next-step x-part.
// chunk 1..4 (= head+1): keyhat in SMEM -> attention -> rv writes.
// Wp chunk (512x64 = 131 KB) is async-staged to SMEM overlapping the gate phase.
__global__ void __launch_bounds__(256) k2_fused(int t, int p, const int* __restrict__ labels,
                                                const float* __restrict__ bl,
                                                const float* __restrict__ Wp,
                                                const float* __restrict__ bp) {
    extern __shared__ float s_wp[];             // 512*64 floats = 131072 B
    __shared__ alignas(16) float s_h[UNITS];
    __shared__ float s_part[4 * CELL];
    __shared__ alignas(16) float s_hid[CELL];   // chunk result; for heads: keyhat after norm
    __shared__ float s_red[2];
    __shared__ float s_att[256];
    __shared__ float s_red2[8];
    __shared__ float s_misc[2];
    __shared__ float s_rvp[4 * CELL];
    int task = blockIdx.x;
    int b = task & 31;
    int chunk = task >> 5;
    int tid = threadIdx.x;
    int lane = tid & 31;
    int warp = tid >> 5;

    // ---- issue async Wp chunk copy (no dependencies; overlaps gates) ----
    {
        const float* wsrc = Wp + chunk * CELL;  // column offset (256B-aligned)
        for (int i = tid; i < (UNITS * CELL) / 4; i += 256) {
            int k = i >> 4;        // row 0..511
            int f = i & 15;        // float4 within 64-col slice
            __pipeline_memcpy_async(((float4*)s_wp) + i,
                                    ((const float4*)(wsrc + (size_t)k * PDIM)) + f, 16);
        }
        __pipeline_commit();
    }

    // ---- gates (redundant per chunk; cheap, removes a kernel boundary) ----
    const float* z0 = g_zpart + (size_t)b * NH;
    const float* z1 = g_zpart + (size_t)(BB + b) * NH;
    const float* z2 = g_zpart + (size_t)(2 * BB + b) * NH;
    for (int u = tid; u < UNITS; u += 256) {
        float zi = z0[u] + z1[u] + z2[u] + bl[u];
        float zf = z0[512 + u] + z1[512 + u] + z2[512 + u] + bl[512 + u];
        float zg = z0[1024 + u] + z1[1024 + u] + z2[1024 + u] + bl[1024 + u];
        float zo = z0[1536 + u] + z1[1536 + u] + z2[1536 + u] + bl[1536 + u];
        float ig = sigm(zi), fg = sigm(zf), og = sigm(zo);
        float gg = ftanh(zg);
        float cold = g_c[(p * BB + b) * UNITS + u];
        float cn = fg * cold + ig * gg;
        float h = og * ftanh(cn);
        s_h[u] = h;
        if (chunk == 0) {
            g_c[((1 - p) * BB + b) * UNITS + u] = cn;
            g_inp[b * KTOT + XDIM + RVDIM + u] = h;
            g_hist[((size_t)t * BB + b) * HRV + u] = h;
        }
    }
    // next-step x part (chunk0 only; disjoint gmem region)
    if (chunk == 0 && t + 1 < TT) {
        if (tid < FEAT) {
            g_inp[b * KTOT + tid] = g_xfeat[((size_t)b * TT + (t + 1)) * FEAT + tid];
        } else if (tid < XDIM) {
            int lab = labels[b * TT + (t + 1)];
            g_inp[b * KTOT + tid] = (tid - FEAT == lab) ? 1.f : 0.f;
        }
    }
    __pipeline_wait_prior(0);
    __syncthreads();

    // ---- Wp GEMV from SMEM: 64 cols, K split in 4 quarters ----
    {
        int j = tid & 63;
        int kq = tid >> 6;
        const float* wrow = s_wp + (kq * 128) * CELL + j;
        const float* hrow = s_h + kq * 128;
        float acc = 0.f;
#pragma unroll 8
        for (int k = 0; k < 128; k++) {
            acc = fmaf(hrow[k], wrow[0], acc);
            wrow += CELL;
        }
        s_part[kq * 64 + j] = acc;
    }
    __syncthreads();
    if (tid < 64) {
        float v = s_part[tid] + s_part[64 + tid] + s_part[128 + tid] + s_part[192 + tid]
                  + bp[chunk * CELL + tid];
        v = ftanh(v);
        s_hid[tid] = v;
        float sq = v * v;
#pragma unroll
        for (int off = 16; off; off >>= 1)
            sq += __shfl_xor_sync(0xffffffffu, sq, off);
        if ((tid & 31) == 0) s_red[tid >> 5] = sq;
    }
    __syncthreads();
    if (tid < 64) {
        float inv = rsqrtf(fmaxf(s_red[0] + s_red[1], 1e-12f));
        float v = s_hid[tid];
        if (chunk == 0) {
            g_wvstore[((size_t)b * TT + t) * CELL + tid] = v;
            g_wvn[((size_t)b * TT + t) * CELL + tid] = v * inv;
        } else {
            s_hid[tid] = v * inv;   // keyhat stays in SMEM
        }
    }
    if (chunk == 0) return;
    __syncthreads();

    // ---- attention scores: quad-split, coalesced ----
    {
        int pq = tid & 3;       // part within quad
        int g = tid >> 2;       // row base (0..63)
        const float4* kh = (const float4*)s_hid;
#pragma unroll
        for (int ss = 0; ss < 4; ss++) {
            int s = g + ss * 64;
            float d = 0.f;
            if (s < t) {
                const float4* wv = (const float4*)(g_wvn + ((size_t)b * TT + s) * CELL);
#pragma unroll
                for (int i = 0; i < 4; i++) {
                    float4 a = kh[i * 4 + pq];
                    float4 v = wv[i * 4 + pq];
                    d = fmaf(a.x, v.x, d); d = fmaf(a.y, v.y, d);
                    d = fmaf(a.z, v.z, d); d = fmaf(a.w, v.w, d);
                }
            }
            d += __shfl_xor_sync(0xffffffffu, d, 1);
            d += __shfl_xor_sync(0xffffffffu, d, 2);
            if (pq == 0 && s < t) s_att[s] = d;
        }
    }
    __syncthreads();

    // ---- softmax over t filled slots + (250 - t) zero slots ----
    float sc = (tid < t) ? s_att[tid] : -1e30f;
    float m = sc;
#pragma unroll
    for (int off = 16; off; off >>= 1) m = fmaxf(m, __shfl_xor_sync(0xffffffffu, m, off));
    if (lane == 0) s_red2[warp] = m;
    __syncthreads();
    if (tid == 0) {
        float mm = 0.f;  // zero slots always exist (t <= 249)
#pragma unroll
        for (int w = 0; w < 8; w++) mm = fmaxf(mm, s_red2[w]);
        s_misc[0] = mm;
    }
    __syncthreads();
    float mfin = s_misc[0];
    float e = (tid < t) ? __expf(sc - mfin) : 0.f;
    s_att[tid] = e;
    float ssum = e;
#pragma unroll
    for (int off = 16; off; off >>= 1) ssum += __shfl_xor_sync(0xffffffffu, ssum, off);
    if (lane == 0) s_red2[warp] = ssum;
    __syncthreads();
    if (tid == 0) {
        float tot = (float)(TT - t) * __expf(-mfin);
#pragma unroll
        for (int w = 0; w < 8; w++) tot += s_red2[w];
        s_misc[1] = 1.f / tot;
    }
    __syncthreads();

    // ---- rv ----
    {
        int c = tid & 63;
        int sg = tid >> 6;
        float acc = 0.f;
        const float* basev = g_wvstore + (size_t)b * TT * CELL + c;
        for (int s = sg; s < t; s += 4)
            acc = fmaf(s_att[s], basev[(size_t)s * CELL], acc);
        s_rvp[sg * 64 + c] = acc;
    }
    __syncthreads();
    if (tid < 64) {
        int head = chunk - 1;
        float rv = (s_rvp[tid] + s_rvp[64 + tid] + s_rvp[128 + tid] + s_rvp[192 + tid])
                   * s_misc[1];
        g_inp[b * KTOT + XDIM + head * CELL + tid] = rv;
        g_hist[((size_t)t * BB + b) * HRV + UNITS + head * CELL + tid] = rv;
    }
}

// ---------------- output head ----------------
__global__ void __launch_bounds__(256) k_out1(const float* __restrict__ Wo,
                                              const float* __restrict__ bo) {
    extern __shared__ float s_in[];  // 32*768 floats (96 KB dynamic)
    int rb = blockIdx.y;
    int cb = blockIdx.x;
    const float4* src = (const float4*)(g_hist + (size_t)rb * 32 * HRV);
    for (int i = threadIdx.x; i < (32 * HRV) / 4; i += 256) ((float4*)s_in)[i] = src[i];
    __syncthreads();
    int lane = threadIdx.x & 31;
    int bg = threadIdx.x >> 5;
    int col = cb * 32 + lane;
    const float* wp = Wo + col;
    const float* ip = s_in + bg * 4 * HRV;
    float a0 = 0.f, a1 = 0.f, a2 = 0.f, a3 = 0.f;
#pragma unroll 8
    for (int k = 0; k < HRV; k += 4) {
        float w0 = wp[0], w1 = wp[UNITS], w2 = wp[2 * UNITS], w3 = wp[3 * UNITS];
        wp += 4 * UNITS;
        float4 x0 = *(const float4*)(ip + k);
        float4 x1 = *(const float4*)(ip + HRV + k);
        float4 x2 = *(const float4*)(ip + 2 * HRV + k);
        float4 x3 = *(const float4*)(ip + 3 * HRV + k);
        a0 = fmaf(w0, x0.x, a0); a0 = fmaf(w1, x0.y, a0); a0 = fmaf(w2, x0.z, a0); a0 = fmaf(w3, x0.w, a0);
        a1 = fmaf(w0, x1.x, a1); a1 = fmaf(w1, x1.y, a1); a1 = fmaf(w2, x1.z, a1); a1 = fmaf(w3, x1.w, a1);
        a2 = fmaf(w0, x2.x, a2); a2 = fmaf(w1, x2.y, a2); a2 = fmaf(w2, x2.z, a2); a2 = fmaf(w3, x2.w, a2);
        a3 = fmaf(w0, x3.x, a3); a3 = fmaf(w1, x3.y, a3); a3 = fmaf(w2, x3.z, a3); a3 = fmaf(w3, x3.w, a3);
    }
    float bv = bo[col];
    int r0 = rb * 32 + bg * 4;
    g_outbuf[(size_t)r0 * UNITS + col] = tanhf(a0 + bv);
    g_outbuf[(size_t)(r0 + 1) * UNITS + col] = tanhf(a1 + bv);
    g_outbuf[(size_t)(r0 + 2) * UNITS + col] = tanhf(a2 + bv);
    g_outbuf[(size_t)(r0 + 3) * UNITS + col] = tanhf(a3 + bv);
}

__global__ void __launch_bounds__(256) k_out2(const float* __restrict__ Wf,
                                              const float* __restrict__ bf,
                                              float* __restrict__ out) {
    __shared__ alignas(16) float s_o[8 * UNITS];
    __shared__ float s_l[8][32];
    __shared__ float s_m[8], s_i[8];
    int nb = blockIdx.x;
    int tid = threadIdx.x;
    const float4* src = (const float4*)(g_outbuf + (size_t)nb * 8 * UNITS);
    for (int i = tid; i < (8 * UNITS) / 4; i += 256) ((float4*)s_o)[i] = src[i];
    __syncthreads();
    if (tid < 200) {
        int r = tid / 25, cls = tid % 25;
        const float* o = s_o + r * UNITS;
        float acc = bf[cls];
        for (int k = 0; k < UNITS; k++) acc = fmaf(o[k], Wf[k * 25 + cls], acc);
        s_l[r][cls] = acc;
    }
    __syncthreads();
    if (tid < 8) {
        float m = -1e30f;
        for (int c = 0; c < 25; c++) m = fmaxf(m, s_l[tid][c]);
        float sm = 0.f;
        for (int c = 0; c < 25; c++) sm += __expf(s_l[tid][c] - m);
        s_m[tid] = m;
        s_i[tid] = 1.f / sm;
    }
    __syncthreads();
    if (tid < 200) {
        int r = tid / 25, cls = tid % 25;
        int n = nb * 8 + r;  // n = t*32 + b
        int tt = n >> 5, bb = n & 31;
        out[((size_t)bb * TT + tt) * 25 + cls] = __expf(s_l[r][cls] - s_m[r]) * s_i[r];
    }
}

// ---------------- launch ----------------
extern "C" void kernel_launch(void* const* d_in, const int* in_sizes, int n_in,
                              void* d_out, int out_size) {
    (void)in_sizes; (void)n_in; (void)out_size;
    const float* images = (const float*)d_in[0];
    const int* labels = (const int*)d_in[1];
    const float* k1 = (const float*)d_in[2];
    const float* cb1 = (const float*)d_in[3];
    const float* g1 = (const float*)d_in[4];
    const float* be1 = (const float*)d_in[5];
    const float* mm1 = (const float*)d_in[6];
    const float* mv1 = (const float*)d_in[7];
    const float* k2 = (const float*)d_in[8];
    const float* cb2 = (const float*)d_in[9];
    const float* g2 = (const float*)d_in[10];
    const float* be2 = (const float*)d_in[11];
    const float* mm2 = (const float*)d_in[12];
    const float* mv2 = (const float*)d_in[13];
    const float* k3 = (const float*)d_in[14];
    const float* cb3 = (const float*)d_in[15];
    const float* g3 = (const float*)d_in[16];
    const float* be3 = (const float*)d_in[17];
    const float* mm3 = (const float*)d_in[18];
    const float* mv3 = (const float*)d_in[19];
    const float* Wx = (const float*)d_in[20];
    const float* Wh = (const float*)d_in[21];
    const float* bl = (const float*)d_in[22];
    const float* Wp = (const float*)d_in[23];
    const float* bp = (const float*)d_in[24];
    const float* Wo = (const float*)d_in[25];
    const float* bo = (const float*)d_in[26];
    const float* Wf = (const float*)d_in[27];
    const float* bf = (const float*)d_in[28];
    float* out = (float*)d_out;

    const int k2_smem = UNITS * CELL * 4;  // 131072 bytes
    cudaFuncSetAttribute(k2_fused, cudaFuncAttributeMaxDynamicSharedMemorySize, k2_smem);
    cudaFuncSetAttribute(k_out1, cudaFuncAttributeMaxDynamicSharedMemorySize, 32 * HRV * 4);

    conv1_k<<<(8000 * 13 * 13 * 8 + 255) / 256, 256>>>(images, k1, cb1, g1, be1, mm1, mv1);
    conv2_k<<<(8000 * 6 * 6 * 16 + 255) / 256, 256>>>(k2, cb2, g2, be2, mm2, mv2);
    conv3_k<<<(8000 * 2 * 2 * 32 + 255) / 256, 256>>>(k3, cb3, g3, be3, mm3, mv3);
    build_wcomb<<<(KTOT * NH + 255) / 256, 256>>>(Wx, Wh);
    k_init<<<BB, 256>>>(labels);

    for (int t = 0; t < TT; t++) {
        k1_zpart<<<dim3(64, 3), 256>>>();
        k2_fused<<<160, 256, k2_smem>>>(t, t & 1, labels, bl, Wp, bp);
    }

    k_out1<<<dim3(16, 250), 256, 32 * HRV * 4>>>(Wo, bo);
    k_out2<<<1000, 256>>>(Wf, bf, out);
}

// round 16
// speedup vs baseline: 1.1032x; 1.1032x over previous
#include <cuda_runtime.h>
#include <math.h>

// ---------------- constants ----------------
#define BB 32
#define TT 250
#define CLASSES 25
#define UNITS 512
#define NH 2048           // 4*UNITS
#define CELL 64
#define HEADS 4
#define FEAT 128
#define XDIM 153          // FEAT + CLASSES
#define RVDIM 256         // HEADS*CELL
#define KTOT 960          // padded (XDIM + RVDIM + UNITS = 921 -> 960)
#define KC 320            // K-chunk for z GEMM (3 chunks)
#define PDIM 320          // (HEADS+1)*CELL
#define HRV 768           // UNITS + RVDIM
#define EPS_BN 1e-3f

// ---------------- device scratch ----------------
__device__ alignas(16) float g_a1[8000 * 13 * 13 * 8];
__device__ alignas(16) float g_a2[8000 * 6 * 6 * 16];
__device__ alignas(16) float g_xfeat[8000 * FEAT];
__device__ alignas(16) float g_Wcomb[KTOT * NH];
__device__ alignas(16) float g_inp[BB * KTOT];
__device__ alignas(16) float g_zpart[3 * BB * NH];
__device__ alignas(16) float g_c[2 * BB * UNITS];        // parity double buffer
__device__ alignas(256) float g_wvstore[BB * TT * CELL]; // raw wv rows
__device__ alignas(256) float g_wvn[BB * TT * CELL];     // normalized wv rows
__device__ alignas(16) float g_hist[TT * BB * HRV];
__device__ alignas(16) float g_outbuf[8000 * UNITS];

__device__ __forceinline__ float sigm(float x) { return 1.f / (1.f + __expf(-x)); }

// ---------------- conv frontend ----------------
__global__ void conv1_k(const float* __restrict__ img, const float* __restrict__ k1,
                        const float* __restrict__ cb, const float* __restrict__ g,
                        const float* __restrict__ be, const float* __restrict__ mm,
                        const float* __restrict__ mv) {
    int idx = blockIdx.x * 256 + threadIdx.x;
    if (idx >= 8000 * 13 * 13 * 8) return;
    int co = idx & 7;
    int t2 = idx >> 3;
    int x = t2 % 13; t2 /= 13;
    int y = t2 % 13; t2 /= 13;
    int bt = t2;
    const float* ip = img + ((size_t)bt * 28 + 2 * y) * 28 + 2 * x;
    float acc = 0.f;
#pragma unroll
    for (int dy = 0; dy < 3; dy++)
#pragma unroll
        for (int dx = 0; dx < 3; dx++)
            acc = fmaf(ip[dy * 28 + dx], k1[(dy * 3 + dx) * 8 + co], acc);
    float sc = g[co] * rsqrtf(mv[co] + EPS_BN);
    float val = (acc + cb[co] - mm[co]) * sc + be[co];
    g_a1[idx] = fmaxf(val, 0.f);
}

__global__ void conv2_k(const float* __restrict__ k2, const float* __restrict__ cb,
                        const float* __restrict__ g, const float* __restrict__ be,
                        const float* __restrict__ mm, const float* __restrict__ mv) {
    int idx = blockIdx.x * 256 + threadIdx.x;
    if (idx >= 8000 * 6 * 6 * 16) return;
    int co = idx & 15;
    int t2 = idx >> 4;
    int x = t2 % 6; t2 /= 6;
    int y = t2 % 6; t2 /= 6;
    int bt = t2;
    const float* ip = g_a1 + (((size_t)bt * 13 + 2 * y) * 13 + 2 * x) * 8;
    float acc = 0.f;
#pragma unroll
    for (int dy = 0; dy < 3; dy++)
#pragma unroll
        for (int dx = 0; dx < 3; dx++) {
            const float* p = ip + (dy * 13 + dx) * 8;
            const float* w = k2 + ((dy * 3 + dx) * 8) * 16 + co;
#pragma unroll
            for (int ci = 0; ci < 8; ci++)
                acc = fmaf(p[ci], w[ci * 16], acc);
        }
    float sc = g[co] * rsqrtf(mv[co] + EPS_BN);
    float val = (acc + cb[co] - mm[co]) * sc + be[co];
    g_a2[idx] = fmaxf(val, 0.f);
}

__global__ void conv3_k(const float* __restrict__ k3, const float* __restrict__ cb,
                        const float* __restrict__ g, const float* __restrict__ be,
                        const float* __restrict__ mm, const float* __restrict__ mv) {
    int idx = blockIdx.x * 256 + threadIdx.x;
    if (idx >= 8000 * 2 * 2 * 32) return;
    int co = idx & 31;
    int x = (idx >> 5) & 1;
    int y = (idx >> 6) & 1;
    int bt = idx >> 7;
    const float* ip = g_a2 + (((size_t)bt * 6 + 2 * y) * 6 + 2 * x) * 16;
    float acc = 0.f;
#pragma unroll
    for (int dy = 0; dy < 3; dy++)
#pragma unroll
        for (int dx = 0; dx < 3; dx++) {
            const float* p = ip + (dy * 6 + dx) * 16;
            const float* w = k3 + ((dy * 3 + dx) * 16) * 32 + co;
#pragma unroll
            for (int ci = 0; ci < 16; ci++)
                acc = fmaf(p[ci], w[ci * 32], acc);
        }
    float sc = g[co] * rsqrtf(mv[co] + EPS_BN);
    float val = (acc + cb[co] - mm[co]) * sc + be[co];
    g_xfeat[idx] = fmaxf(val, 0.f);
}

// ---------------- Wcomb build + init ----------------
__global__ void build_wcomb(const float* __restrict__ Wx, const float* __restrict__ Wh) {
    int idx = blockIdx.x * 256 + threadIdx.x;
    if (idx >= KTOT * NH) return;
    int r = idx >> 11;
    int c = idx & 2047;
    float v = 0.f;
    if (r < 409) v = Wx[r * NH + c];
    else if (r < 921) v = Wh[(r - 409) * NH + c];
    g_Wcomb[idx] = v;
}

__global__ void k_init(const int* __restrict__ labels) {
    int b = blockIdx.x;
    for (int u = threadIdx.x; u < UNITS; u += 256) g_c[b * UNITS + u] = 0.f;  // parity 0
    int lab = labels[b * TT];  // t=0
    for (int k = threadIdx.x; k < KTOT; k += 256) {
        float v = 0.f;
        if (k < FEAT) v = g_xfeat[(size_t)b * TT * FEAT + k];
        else if (k < XDIM) v = (k - FEAT == lab) ? 1.f : 0.f;
        g_inp[b * KTOT + k] = v;
    }
}

// ---------------- K1: partial z GEMM ----------------
// grid (64, 3), block 256. Block = 32 cols x 32 batches over one K-chunk.
__global__ void __launch_bounds__(256) k1_zpart() {
    __shared__ alignas(16) float s_in[BB * KC];  // 40 KB
    int kc = blockIdx.y;
    int kbase = kc * KC;
    for (int i = threadIdx.x; i < (BB * KC) / 4; i += 256) {
        int b = i / (KC / 4);
        int k4 = i - b * (KC / 4);
        ((float4*)s_in)[i] = *(const float4*)(g_inp + b * KTOT + kbase + 4 * k4);
    }
    __syncthreads();
    int lane = threadIdx.x & 31;
    int bg = threadIdx.x >> 5;
    int col = (blockIdx.x << 5) + lane;
    const float* wp = g_Wcomb + (size_t)kbase * NH + col;
    const float* ip = s_in + bg * 4 * KC;
    float a0 = 0.f, a1 = 0.f, a2 = 0.f, a3 = 0.f;
#pragma unroll 8
    for (int k = 0; k < KC; k += 4) {
        float w0 = wp[0], w1 = wp[NH], w2 = wp[2 * NH], w3 = wp[3 * NH];
        wp += 4 * NH;
        float4 x0 = *(const float4*)(ip + k);
        float4 x1 = *(const float4*)(ip + KC + k);
        float4 x2 = *(const float4*)(ip + 2 * KC + k);
        float4 x3 = *(const float4*)(ip + 3 * KC + k);
        a0 = fmaf(w0, x0.x, a0); a0 = fmaf(w1, x0.y, a0); a0 = fmaf(w2, x0.z, a0); a0 = fmaf(w3, x0.w, a0);
        a1 = fmaf(w0, x1.x, a1); a1 = fmaf(w1, x1.y, a1); a1 = fmaf(w2, x1.z, a1); a1 = fmaf(w3, x1.w, a1);
        a2 = fmaf(w0, x2.x, a2); a2 = fmaf(w1, x2.y, a2); a2 = fmaf(w2, x2.z, a2); a2 = fmaf(w3, x2.w, a2);
        a3 = fmaf(w0, x3.x, a3); a3 = fmaf(w1, x3.y, a3); a3 = fmaf(w2, x3.z, a3); a3 = fmaf(w3, x3.w, a3);
    }
    int b0 = bg << 2;
    float* zp = g_zpart + ((size_t)(kc * BB + b0)) * NH + col;
    zp[0] = a0; zp[NH] = a1; zp[2 * NH] = a2; zp[3 * NH] = a3;
}

// ---------------- K2 fused: gates + Wp + norm + attention ----------------
// grid 128 = (b in 0..31) x (head 0..3) — single wave on 148 SMs.
// head 0 block additionally handles the wv chunk (Wp cols 0..63): double-width
// GEMV (cols 0..127 over 2 K-halves), c/h/next-x writes, wv/wvn stores.
// heads 1..3: 64-col GEMV over 4 K-quarters (cols (head+1)*64..).
__global__ void __launch_bounds__(256) k2_fused(int t, int p, const int* __restrict__ labels,
                                                const float* __restrict__ bl,
                                                const float* __restrict__ Wp,
                                                const float* __restrict__ bp) {
    __shared__ alignas(16) float s_h[UNITS];
    __shared__ float s_part[2 * 128];           // head0: [2][128]; others: [4][64]
    __shared__ alignas(16) float s_hid[128];
    __shared__ alignas(16) float s_kh[CELL];    // keyhat for this block's head
    __shared__ float s_red[4];
    __shared__ float s_att[256];
    __shared__ float s_red2[8];
    __shared__ float s_misc[2];
    __shared__ float s_rvp[4 * CELL];
    int b = blockIdx.x & 31;
    int head = blockIdx.x >> 5;
    int tid = threadIdx.x;
    int lane = tid & 31;
    int warp = tid >> 5;

    // ---- gates (redundant per head; removes a kernel boundary) ----
    const float* z0 = g_zpart + (size_t)b * NH;
    const float* z1 = g_zpart + (size_t)(BB + b) * NH;
    const float* z2 = g_zpart + (size_t)(2 * BB + b) * NH;
    for (int u = tid; u < UNITS; u += 256) {
        float zi = z0[u] + z1[u] + z2[u] + bl[u];
        float zf = z0[512 + u] + z1[512 + u] + z2[512 + u] + bl[512 + u];
        float zg = z0[1024 + u] + z1[1024 + u] + z2[1024 + u] + bl[1024 + u];
        float zo = z0[1536 + u] + z1[1536 + u] + z2[1536 + u] + bl[1536 + u];
        float ig = sigm(zi), fg = sigm(zf), og = sigm(zo);
        float gg = tanhf(zg);
        float cold = g_c[(p * BB + b) * UNITS + u];
        float cn = fg * cold + ig * gg;
        float h = og * tanhf(cn);
        s_h[u] = h;
        if (head == 0) {
            g_c[((1 - p) * BB + b) * UNITS + u] = cn;
            g_inp[b * KTOT + XDIM + RVDIM + u] = h;
            g_hist[((size_t)t * BB + b) * HRV + u] = h;
        }
    }
    // next-step x part (head0 only; disjoint gmem region)
    if (head == 0 && t + 1 < TT) {
        if (tid < FEAT) {
            g_inp[b * KTOT + tid] = g_xfeat[((size_t)b * TT + (t + 1)) * FEAT + tid];
        } else if (tid < XDIM) {
            int lab = labels[b * TT + (t + 1)];
            g_inp[b * KTOT + tid] = (tid - FEAT == lab) ? 1.f : 0.f;
        }
    }
    __syncthreads();

    // ---- Wp GEMV ----
    if (head == 0) {
        // 128 cols (wv + head0 keys), K split in 2 halves
        int j = tid & 127;
        int kq = tid >> 7;
        const float* w = Wp + (size_t)(kq * 256) * PDIM + j;
        const float* hrow = s_h + kq * 256;
        float acc = 0.f;
#pragma unroll 16
        for (int k = 0; k < 256; k++) {
            acc = fmaf(hrow[k], w[0], acc);
            w += PDIM;
        }
        s_part[kq * 128 + j] = acc;
    } else {
        // 64 cols, K split in 4 quarters
        int j = tid & 63;
        int kq = tid >> 6;
        const float* w = Wp + (size_t)(kq * 128) * PDIM + (head + 1) * CELL + j;
        const float* hrow = s_h + kq * 128;
        float acc = 0.f;
#pragma unroll 16
        for (int k = 0; k < 128; k++) {
            acc = fmaf(hrow[k], w[0], acc);
            w += PDIM;
        }
        s_part[kq * 64 + j] = acc;
    }
    __syncthreads();

    if (head == 0) {
        if (tid < 128) {
            float v = s_part[tid] + s_part[128 + tid] + bp[tid];
            v = tanhf(v);
            s_hid[tid] = v;
            float sq = v * v;
#pragma unroll
            for (int off = 16; off; off >>= 1)
                sq += __shfl_xor_sync(0xffffffffu, sq, off);
            if (lane == 0) s_red[warp] = sq;   // warps 0..3
        }
        __syncthreads();
        if (tid < 128) {
            int grp = tid >> 6;  // 0 = wv, 1 = head0 keys
            float inv = rsqrtf(fmaxf(s_red[2 * grp] + s_red[2 * grp + 1], 1e-12f));
            float v = s_hid[tid];
            if (tid < 64) {
                g_wvstore[((size_t)b * TT + t) * CELL + tid] = v;
                g_wvn[((size_t)b * TT + t) * CELL + tid] = v * inv;
            } else {
                s_kh[tid - 64] = v * inv;
            }
        }
    } else {
        if (tid < 64) {
            float v = s_part[tid] + s_part[64 + tid] + s_part[128 + tid] + s_part[192 + tid]
                      + bp[(head + 1) * CELL + tid];
            v = tanhf(v);
            s_hid[tid] = v;
            float sq = v * v;
#pragma unroll
            for (int off = 16; off; off >>= 1)
                sq += __shfl_xor_sync(0xffffffffu, sq, off);
            if ((tid & 31) == 0) s_red[tid >> 5] = sq;
        }
        __syncthreads();
        if (tid < 64) {
            float inv = rsqrtf(fmaxf(s_red[0] + s_red[1], 1e-12f));
            s_kh[tid] = s_hid[tid] * inv;
        }
    }
    __syncthreads();

    // ---- attention scores: quad-split, coalesced ----
    {
        int pq = tid & 3;       // part within quad
        int g = tid >> 2;       // row base (0..63)
        const float4* kh = (const float4*)s_kh;
#pragma unroll
        for (int ss = 0; ss < 4; ss++) {
            int s = g + ss * 64;
            float d = 0.f;
            if (s < t) {
                const float4* wv = (const float4*)(g_wvn + ((size_t)b * TT + s) * CELL);
#pragma unroll
                for (int i = 0; i < 4; i++) {
                    float4 a = kh[i * 4 + pq];
                    float4 v = wv[i * 4 + pq];
                    d = fmaf(a.x, v.x, d); d = fmaf(a.y, v.y, d);
                    d = fmaf(a.z, v.z, d); d = fmaf(a.w, v.w, d);
                }
            }
            d += __shfl_xor_sync(0xffffffffu, d, 1);
            d += __shfl_xor_sync(0xffffffffu, d, 2);
            if (pq == 0 && s < t) s_att[s] = d;
        }
    }
    __syncthreads();

    // ---- softmax over t filled slots + (250 - t) zero slots ----
    float sc = (tid < t) ? s_att[tid] : -1e30f;
    float m = sc;
#pragma unroll
    for (int off = 16; off; off >>= 1) m = fmaxf(m, __shfl_xor_sync(0xffffffffu, m, off));
    if (lane == 0) s_red2[warp] = m;
    __syncthreads();
    if (tid == 0) {
        float mm = 0.f;  // zero slots always exist (t <= 249)
#pragma unroll
        for (int w = 0; w < 8; w++) mm = fmaxf(mm, s_red2[w]);
        s_misc[0] = mm;
    }
    __syncthreads();
    float mfin = s_misc[0];
    float e = (tid < t) ? __expf(sc - mfin) : 0.f;
    s_att[tid] = e;
    float ssum = e;
#pragma unroll
    for (int off = 16; off; off >>= 1) ssum += __shfl_xor_sync(0xffffffffu, ssum, off);
    if (lane == 0) s_red2[warp] = ssum;
    __syncthreads();
    if (tid == 0) {
        float tot = (float)(TT - t) * __expf(-mfin);
#pragma unroll
        for (int w = 0; w < 8; w++) tot += s_red2[w];
        s_misc[1] = 1.f / tot;
    }
    __syncthreads();

    // ---- rv ----
    {
        int c = tid & 63;
        int sg = tid >> 6;
        float acc = 0.f;
        const float* basev = g_wvstore + (size_t)b * TT * CELL + c;
#pragma unroll 4
        for (int s = sg; s < t; s += 4)
            acc = fmaf(s_att[s], basev[(size_t)s * CELL], acc);
        s_rvp[sg * 64 + c] = acc;
    }
    __syncthreads();
    if (tid < 64) {
        float rv = (s_rvp[tid] + s_rvp[64 + tid] + s_rvp[128 + tid] + s_rvp[192 + tid])
                   * s_misc[1];
        g_inp[b * KTOT + XDIM + head * CELL + tid] = rv;
        g_hist[((size_t)t * BB + b) * HRV + UNITS + head * CELL + tid] = rv;
    }
}

// ---------------- output head ----------------
__global__ void __launch_bounds__(256) k_out1(const float* __restrict__ Wo,
                                              const float* __restrict__ bo) {
    extern __shared__ float s_in[];  // 32*768 floats (96 KB dynamic)
    int rb = blockIdx.y;
    int cb = blockIdx.x;
    const float4* src = (const float4*)(g_hist + (size_t)rb * 32 * HRV);
    for (int i = threadIdx.x; i < (32 * HRV) / 4; i += 256) ((float4*)s_in)[i] = src[i];
    __syncthreads();
    int lane = threadIdx.x & 31;
    int bg = threadIdx.x >> 5;
    int col = cb * 32 + lane;
    const float* wp = Wo + col;
    const float* ip = s_in + bg * 4 * HRV;
    float a0 = 0.f, a1 = 0.f, a2 = 0.f, a3 = 0.f;
#pragma unroll 8
    for (int k = 0; k < HRV; k += 4) {
        float w0 = wp[0], w1 = wp[UNITS], w2 = wp[2 * UNITS], w3 = wp[3 * UNITS];
        wp += 4 * UNITS;
        float4 x0 = *(const float4*)(ip + k);
        float4 x1 = *(const float4*)(ip + HRV + k);
        float4 x2 = *(const float4*)(ip + 2 * HRV + k);
        float4 x3 = *(const float4*)(ip + 3 * HRV + k);
        a0 = fmaf(w0, x0.x, a0); a0 = fmaf(w1, x0.y, a0); a0 = fmaf(w2, x0.z, a0); a0 = fmaf(w3, x0.w, a0);
        a1 = fmaf(w0, x1.x, a1); a1 = fmaf(w1, x1.y, a1); a1 = fmaf(w2, x1.z, a1); a1 = fmaf(w3, x1.w, a1);
        a2 = fmaf(w0, x2.x, a2); a2 = fmaf(w1, x2.y, a2); a2 = fmaf(w2, x2.z, a2); a2 = fmaf(w3, x2.w, a2);
        a3 = fmaf(w0, x3.x, a3); a3 = fmaf(w1, x3.y, a3); a3 = fmaf(w2, x3.z, a3); a3 = fmaf(w3, x3.w, a3);
    }
    float bv = bo[col];
    int r0 = rb * 32 + bg * 4;
    g_outbuf[(size_t)r0 * UNITS + col] = tanhf(a0 + bv);
    g_outbuf[(size_t)(r0 + 1) * UNITS + col] = tanhf(a1 + bv);
    g_outbuf[(size_t)(r0 + 2) * UNITS + col] = tanhf(a2 + bv);
    g_outbuf[(size_t)(r0 + 3) * UNITS + col] = tanhf(a3 + bv);
}

__global__ void __launch_bounds__(256) k_out2(const float* __restrict__ Wf,
                                              const float* __restrict__ bf,
                                              float* __restrict__ out) {
    __shared__ alignas(16) float s_o[8 * UNITS];
    __shared__ float s_l[8][32];
    __shared__ float s_m[8], s_i[8];
    int nb = blockIdx.x;
    int tid = threadIdx.x;
    const float4* src = (const float4*)(g_outbuf + (size_t)nb * 8 * UNITS);
    for (int i = tid; i < (8 * UNITS) / 4; i += 256) ((float4*)s_o)[i] = src[i];
    __syncthreads();
    if (tid < 200) {
        int r = tid / 25, cls = tid % 25;
        const float* o = s_o + r * UNITS;
        float acc = bf[cls];
        for (int k = 0; k < UNITS; k++) acc = fmaf(o[k], Wf[k * 25 + cls], acc);
        s_l[r][cls] = acc;
    }
    __syncthreads();
    if (tid < 8) {
        float m = -1e30f;
        for (int c = 0; c < 25; c++) m = fmaxf(m, s_l[tid][c]);
        float sm = 0.f;
        for (int c = 0; c < 25; c++) sm += __expf(s_l[tid][c] - m);
        s_m[tid] = m;
        s_i[tid] = 1.f / sm;
    }
    __syncthreads();
    if (tid < 200) {
        int r = tid / 25, cls = tid % 25;
        int n = nb * 8 + r;  // n = t*32 + b
        int tt = n >> 5, bb = n & 31;
        out[((size_t)bb * TT + tt) * 25 + cls] = __expf(s_l[r][cls] - s_m[r]) * s_i[r];
    }
}

// ---------------- launch ----------------
extern "C" void kernel_launch(void* const* d_in, const int* in_sizes, int n_in,
                              void* d_out, int out_size) {
    (void)in_sizes; (void)n_in; (void)out_size;
    const float* images = (const float*)d_in[0];
    const int* labels = (const int*)d_in[1];
    const float* k1 = (const float*)d_in[2];
    const float* cb1 = (const float*)d_in[3];
    const float* g1 = (const float*)d_in[4];
    const float* be1 = (const float*)d_in[5];
    const float* mm1 = (const float*)d_in[6];
    const float* mv1 = (const float*)d_in[7];
    const float* k2 = (const float*)d_in[8];
    const float* cb2 = (const float*)d_in[9];
    const float* g2 = (const float*)d_in[10];
    const float* be2 = (const float*)d_in[11];
    const float* mm2 = (const float*)d_in[12];
    const float* mv2 = (const float*)d_in[13];
    const float* k3 = (const float*)d_in[14];
    const float* cb3 = (const float*)d_in[15];
    const float* g3 = (const float*)d_in[16];
    const float* be3 = (const float*)d_in[17];
    const float* mm3 = (const float*)d_in[18];
    const float* mv3 = (const float*)d_in[19];
    const float* Wx = (const float*)d_in[20];
    const float* Wh = (const float*)d_in[21];
    const float* bl = (const float*)d_in[22];
    const float* Wp = (const float*)d_in[23];
    const float* bp = (const float*)d_in[24];
    const float* Wo = (const float*)d_in[25];
    const float* bo = (const float*)d_in[26];
    const float* Wf = (const float*)d_in[27];
    const float* bf = (const float*)d_in[28];
    float* out = (float*)d_out;

    cudaFuncSetAttribute(k_out1, cudaFuncAttributeMaxDynamicSharedMemorySize, 32 * HRV * 4);

    conv1_k<<<(8000 * 13 * 13 * 8 + 255) / 256, 256>>>(images, k1, cb1, g1, be1, mm1, mv1);
    conv2_k<<<(8000 * 6 * 6 * 16 + 255) / 256, 256>>>(k2, cb2, g2, be2, mm2, mv2);
    conv3_k<<<(8000 * 2 * 2 * 32 + 255) / 256, 256>>>(k3, cb3, g3, be3, mm3, mv3);
    build_wcomb<<<(KTOT * NH + 255) / 256, 256>>>(Wx, Wh);
    k_init<<<BB, 256>>>(labels);

    for (int t = 0; t < TT; t++) {
        k1_zpart<<<dim3(64, 3), 256>>>();
        k2_fused<<<128, 256>>>(t, t & 1, labels, bl, Wp, bp);
    }

    k_out1<<<dim3(16, 250), 256, 32 * HRV * 4>>>(Wo, bo);
    k_out2<<<1000, 256>>>(Wf, bf, out);
}